// round 6
// baseline (speedup 1.0000x reference)
#include <cuda_runtime.h>
#include <cstdint>
#include <math.h>

#define BB 8192
#define KD 256
#define MD 1024
#define TT 10

#define SROW 40                     // floats per smem row: 16 (hi,lo) pairs + 8 pad (P mod 32 == 8 -> conflict-free float2 LDS)
#define TS (128 * SROW)             // tile floats (5120)
#define SMEM_BYTES (4 * TS * 4)     // 81920 B

// ---------------- scratch ----------------
// interleaved (hi,lo) pair tensors
__device__ float g_Rp[512 * 512 * 2];
__device__ float g_WXrp[512 * 256 * 2];
__device__ float g_Ep[1024 * 512 * 2];
__device__ float g_Dp[512 * 1024 * 2];
__device__ float g_ypair[(size_t)BB * 256 * 2];
__device__ float g_xpair[(size_t)BB * 512 * 2];
__device__ float g_xmappair[(size_t)BB * 512 * 2];
__device__ float g_xsppair[(size_t)BB * 1024 * 2];
// fp32 tensors
__device__ float g_x[(size_t)BB * 512];
__device__ float g_xmap[(size_t)BB * 512];
__device__ float g_b0[(size_t)BB * 512];
__device__ float g_acc[3];

// ---------------- asm helpers ----------------
__device__ __forceinline__ uint32_t smem_u32(const void* p) {
    uint32_t a;
    asm("{ .reg .u64 t; cvta.to.shared.u64 t, %1; cvt.u32.u64 %0, t; }" : "=r"(a) : "l"(p));
    return a;
}
__device__ __forceinline__ void cp16(uint32_t dst, const void* src) {
    asm volatile("cp.async.cg.shared.global [%0], [%1], 16;" :: "r"(dst), "l"(src));
}
__device__ __forceinline__ void cp_commit() {
    asm volatile("cp.async.commit_group;" ::: "memory");
}
template <int N>
__device__ __forceinline__ void cp_wait() {
    asm volatile("cp.async.wait_group %0;" :: "n"(N) : "memory");
}
__device__ __forceinline__ void mma8(float* c, uint32_t a0, uint32_t a1, uint32_t a2, uint32_t a3,
                                     uint32_t b0, uint32_t b1) {
    asm volatile(
        "mma.sync.aligned.m16n8k8.row.col.f32.tf32.tf32.f32 "
        "{%0,%1,%2,%3}, {%4,%5,%6,%7}, {%8,%9}, {%0,%1,%2,%3};"
        : "+f"(c[0]), "+f"(c[1]), "+f"(c[2]), "+f"(c[3])
        : "r"(a0), "r"(a1), "r"(a2), "r"(a3), "r"(b0), "r"(b1));
}
__device__ __forceinline__ float2 splitf(float v) {
    uint32_t hb, lb;
    asm("cvt.rna.tf32.f32 %0, %1;" : "=r"(hb) : "f"(v));
    float lo = v - __uint_as_float(hb);
    asm("cvt.rna.tf32.f32 %0, %1;" : "=r"(lb) : "f"(lo));
    return make_float2(__uint_as_float(hb), __uint_as_float(lb));
}
#define U(x) __float_as_uint(x)

// ---------------- tensor-core GEMM: D[m][b] = sum_k A[m][k] * X[b][k] ----------------
// Operands are pre-split (hi,lo) interleaved float2 tensors.
// EPI: 0 = b0 (+x=gamma*b0), 1 = x-update, 2 = shrink(+L1,+count), 3 = xmap(+huber)
template <int KIN, int MOUT, int EPI>
__global__ void __launch_bounds__(256, 2) k_gemm(
    const float* __restrict__ Ap, const float* __restrict__ Xp,
    float* __restrict__ OUT, float* __restrict__ OUT2, float* __restrict__ OUTP,
    const float* __restrict__ aux1, const float* __restrict__ aux2,
    const float* __restrict__ scal, int last)
{
    extern __shared__ float sm[];
    const int tid = threadIdx.x;
    const int wid = tid >> 5, lane = tid & 31;
    const int g = lane >> 2, tg = lane & 3;
    const int bb0 = blockIdx.x * 128;
    const int m0 = blockIdx.y * 128;
    const int m_off = (wid & 1) * 64;
    const int n_off = (wid >> 1) * 32;

    constexpr int NS = KIN / 16;

    auto issue = [&](int st) {
        const int kk = st * 16;
        float* Ab = sm + (st & 1) * TS;
        float* Xb = sm + 2 * TS + (st & 1) * TS;
#pragma unroll
        for (int r = 0; r < 4; r++) {
            int ch = tid + 256 * r;
            int row = ch >> 3, cc = ch & 7;
            cp16(smem_u32(Ab + row * SROW + cc * 4),
                 Ap + (((size_t)(m0 + row) * KIN + kk + cc * 2) << 1));
            cp16(smem_u32(Xb + row * SROW + cc * 4),
                 Xp + (((size_t)(bb0 + row) * KIN + kk + cc * 2) << 1));
        }
        cp_commit();
    };

    float c[4][4][4];
#pragma unroll
    for (int i = 0; i < 4; i++)
#pragma unroll
        for (int j = 0; j < 4; j++)
#pragma unroll
            for (int q = 0; q < 4; q++) c[i][j][q] = 0.f;

    issue(0);
    issue(1);

    for (int kt = 0; kt < NS; kt++) {
        cp_wait<1>();
        __syncthreads();
        const float* Ab = sm + (kt & 1) * TS;
        const float* Xb = sm + 2 * TS + (kt & 1) * TS;
#pragma unroll
        for (int ks = 0; ks < 2; ks++) {
            const float* ap = Ab + (m_off + g) * SROW + (ks * 8 + tg) * 2;
            const float* xp = Xb + (n_off + g) * SROW + (ks * 8 + tg) * 2;
            float2 a0[4], a1[4], a2[4], a3[4], x0[4], x1[4];
#pragma unroll
            for (int mf = 0; mf < 4; mf++) {
                a0[mf] = *(const float2*)(ap + mf * 640);
                a1[mf] = *(const float2*)(ap + mf * 640 + 320);
                a2[mf] = *(const float2*)(ap + mf * 640 + 8);
                a3[mf] = *(const float2*)(ap + mf * 640 + 328);
            }
#pragma unroll
            for (int nf = 0; nf < 4; nf++) {
                x0[nf] = *(const float2*)(xp + nf * 320);
                x1[nf] = *(const float2*)(xp + nf * 320 + 8);
            }
            // Pass 1: hi*hi over all 16 independent accumulators (no RAW chains)
#pragma unroll
            for (int mf = 0; mf < 4; mf++)
#pragma unroll
                for (int nf = 0; nf < 4; nf++)
                    mma8(c[mf][nf], U(a0[mf].x), U(a1[mf].x), U(a2[mf].x), U(a3[mf].x),
                         U(x0[nf].x), U(x1[nf].x));
            // Pass 2: hi*lo
#pragma unroll
            for (int mf = 0; mf < 4; mf++)
#pragma unroll
                for (int nf = 0; nf < 4; nf++)
                    mma8(c[mf][nf], U(a0[mf].x), U(a1[mf].x), U(a2[mf].x), U(a3[mf].x),
                         U(x0[nf].y), U(x1[nf].y));
            // Pass 3: lo*hi
#pragma unroll
            for (int mf = 0; mf < 4; mf++)
#pragma unroll
                for (int nf = 0; nf < 4; nf++)
                    mma8(c[mf][nf], U(a0[mf].y), U(a1[mf].y), U(a2[mf].y), U(a3[mf].y),
                         U(x0[nf].x), U(x1[nf].x));
        }
        __syncthreads();
        if (kt + 2 < NS) issue(kt + 2);
        else cp_commit();
    }

    // ---------------- epilogue (32-bit indexing) ----------------
    float s_a = 0.f, s_b = 0.f;
    float gam = 0.f, eta = 0.f;
    if (EPI == 0 || EPI == 1) gam = scal[0];
    if (EPI == 2) eta = scal[0];
    const uint32_t mbase = (uint32_t)(m0 + m_off) + (uint32_t)g;
    const uint32_t bbase = (uint32_t)(bb0 + n_off) + (uint32_t)(tg * 2);
#pragma unroll
    for (int mf = 0; mf < 4; mf++)
#pragma unroll
        for (int nf = 0; nf < 4; nf++) {
#pragma unroll
            for (int q = 0; q < 4; q++) {
                uint32_t m = mbase + mf * 16 + (q >= 2 ? 8 : 0);
                uint32_t b = bbase + nf * 8 + (q & 1);
                uint32_t o = b * (uint32_t)MOUT + m;
                float d = c[mf][nf][q];
                if (EPI == 0) {
                    OUT[o] = d;                 // b0
                    float xv = gam * d;         // x1 = gamma1 * b0
                    OUT2[o] = xv;
                    *(float2*)(OUTP + 2 * (size_t)o) = splitf(xv);
                } else if (EPI == 1) {
                    float v = aux1[o] - gam * (d - aux2[o]);
                    OUT[o] = v;
                    *(float2*)(OUTP + 2 * (size_t)o) = splitf(v);
                } else if (EPI == 2) {
                    float ad = fabsf(d) - eta;
                    float v = (ad > 0.f) ? copysignf(ad, d) : 0.f;
                    *(float2*)(OUTP + 2 * (size_t)o) = splitf(v);
                    s_a += fabsf(v);
                    if (last) s_b += (fabsf(v) > 1e-3f) ? 1.f : 0.f;
                } else {
                    float xo = aux1[o];
                    float dd = xo - d; float ad = fabsf(dd);
                    s_a += (ad < 1.f) ? 0.5f * dd * dd : ad - 0.5f;
                    OUT[o] = d;
                    *(float2*)(OUTP + 2 * (size_t)o) = splitf(d);
                }
            }
        }
    if (EPI == 2 || EPI == 3) {
#pragma unroll
        for (int off = 16; off > 0; off >>= 1) {
            s_a += __shfl_down_sync(0xffffffffu, s_a, off);
            if (EPI == 2) s_b += __shfl_down_sync(0xffffffffu, s_b, off);
        }
        if (lane == 0) {
            atomicAdd(&g_acc[EPI == 2 ? 0 : 1], s_a);
            if (EPI == 2 && last) atomicAdd(&g_acc[2], s_b);
        }
    }
}

// ---------------- prep kernels ----------------
// R pairs + acc zero
__global__ void k_prepA(const float* __restrict__ W, const float* __restrict__ WX) {
    int j = blockIdx.x * 16 + threadIdx.x;   // 0..255
    int i = blockIdx.y * 16 + threadIdx.y;   // 0..255
    if (i == 0 && j < 3) g_acc[j] = 0.f;
    float pre = 0.f, pim = 0.f;
#pragma unroll 4
    for (int n = 0; n < 128; n++) {
        float ar = WX[i * 128 + n], ai = WX[32768 + i * 128 + n];
        float br = W[n * 256 + j],  bi = W[32768 + n * 256 + j];
        pre += ar * br - ai * bi;
        pim += ar * bi + ai * br;
    }
    *(float2*)&g_Rp[2 * (i * 512 + j)]               = splitf(pre);
    *(float2*)&g_Rp[2 * (i * 512 + j + 256)]         = splitf(-pim);
    *(float2*)&g_Rp[2 * ((i + 256) * 512 + j)]       = splitf(pim);
    *(float2*)&g_Rp[2 * ((i + 256) * 512 + j + 256)] = splitf(pre);
}

// WXr / E / D / y pairs, one grid-stride kernel
__global__ void k_prepB(const float* __restrict__ E0, const float* __restrict__ WX,
                        const float* __restrict__ y) {
    size_t idx = (size_t)blockIdx.x * 256 + threadIdx.x;
    if (idx < 131072) {                           // WXr [512][256]
        int np = (int)idx & 255, j = (int)idx >> 8;
        int jj = j & 255, jr = j >> 8;
        int nn = np & 127, nc = np >> 7;
        float re = WX[jj * 128 + nn], im = WX[32768 + jj * 128 + nn];
        float v = (jr == 0) ? ((nc == 0) ? re : -im) : ((nc == 0) ? im : re);
        *(float2*)&g_WXrp[2 * idx] = splitf(v);
    } else if (idx < 131072 + 524288) {           // E [1024][512]
        size_t t = idx - 131072;
        int k = (int)t & 511, mrow = (int)(t >> 9);
        float v = (k < 256) ? E0[mrow * 256 + k] : -E0[262144 + mrow * 256 + (k - 256)];
        *(float2*)&g_Ep[2 * t] = splitf(v);
    } else if (idx < 131072 + 2 * 524288) {       // D [512][1024]
        size_t t = idx - 131072 - 524288;
        int mrow = (int)t & 1023, j = (int)(t >> 10);
        float v = (j < 256) ? E0[mrow * 256 + j] : -E0[262144 + mrow * 256 + (j - 256)];
        *(float2*)&g_Dp[2 * t] = splitf(v);
    } else {                                      // y [8192][256]
        size_t t = idx - 131072 - 2 * 524288;
        *(float2*)&g_ypair[2 * t] = splitf(y[t]);
    }
}

__global__ void k_final(float* __restrict__ out) {
    int idx = blockIdx.x * 256 + threadIdx.x;          // 2*8192*256
    int k = idx & 255, b = (idx >> 8) & 8191, cch = idx >> 21;
    out[idx] = g_xmap[(size_t)b * 512 + cch * 256 + k];
}

__global__ void k_scalars(float* __restrict__ out) {
    if (threadIdx.x == 0 && blockIdx.x == 0) {
        size_t base = 2ull * BB * KD;
        out[base + 0] = g_acc[0] / (float)BB;
        out[base + 1] = g_acc[1] / ((float)2 * KD * BB * TT);
        out[base + 2] = g_acc[2] / (float)BB;
    }
}

// ---------------- launch ----------------
extern "C" void kernel_launch(void* const* d_in, const int* in_sizes, int n_in,
                              void* d_out, int out_size) {
    const float* y      = (const float*)d_in[0];
    const float* W      = (const float*)d_in[1];
    const float* WX     = (const float*)d_in[2];
    const float* E0     = (const float*)d_in[3];
    const float* etas   = (const float*)d_in[4];
    const float* gammas = (const float*)d_in[5];
    float* out = (float*)d_out;

    void *pRp, *pWXrp, *pEp, *pDp, *pYp, *pXp, *pXmp, *pXsp, *pX, *pXm, *pB0;
    cudaGetSymbolAddress(&pRp, g_Rp);
    cudaGetSymbolAddress(&pWXrp, g_WXrp);
    cudaGetSymbolAddress(&pEp, g_Ep);
    cudaGetSymbolAddress(&pDp, g_Dp);
    cudaGetSymbolAddress(&pYp, g_ypair);
    cudaGetSymbolAddress(&pXp, g_xpair);
    cudaGetSymbolAddress(&pXmp, g_xmappair);
    cudaGetSymbolAddress(&pXsp, g_xsppair);
    cudaGetSymbolAddress(&pX, g_x);
    cudaGetSymbolAddress(&pXm, g_xmap);
    cudaGetSymbolAddress(&pB0, g_b0);
    const float *fRp = (const float*)pRp, *fWXrp = (const float*)pWXrp;
    const float *fEp = (const float*)pEp, *fDp = (const float*)pDp;
    const float *fYp = (const float*)pYp;
    float *fXp = (float*)pXp, *fXmp = (float*)pXmp, *fXsp = (float*)pXsp;
    float *fX = (float*)pX, *fXm = (float*)pXm, *fB0 = (float*)pB0;

    cudaFuncSetAttribute(k_gemm<256, 512, 0>, cudaFuncAttributeMaxDynamicSharedMemorySize, SMEM_BYTES);
    cudaFuncSetAttribute(k_gemm<512, 512, 1>, cudaFuncAttributeMaxDynamicSharedMemorySize, SMEM_BYTES);
    cudaFuncSetAttribute(k_gemm<512, 1024, 2>, cudaFuncAttributeMaxDynamicSharedMemorySize, SMEM_BYTES);
    cudaFuncSetAttribute(k_gemm<1024, 512, 3>, cudaFuncAttributeMaxDynamicSharedMemorySize, SMEM_BYTES);

    k_prepA<<<dim3(16, 16), dim3(16, 16)>>>(W, WX);
    k_prepB<<<(131072 + 2 * 524288 + 2097152) / 256, 256>>>(E0, WX, y);

    // b0 = WXr.y ; x1 = gamma1*b0 (fused)
    k_gemm<256, 512, 0><<<dim3(BB / 128, 4), 256, SMEM_BYTES>>>(
        fWXrp, fYp, fB0, fX, fXp, nullptr, nullptr, gammas + 1, 0);

    for (int i = 1; i <= TT; i++) {
        if (i > 1)
            k_gemm<512, 512, 1><<<dim3(BB / 128, 4), 256, SMEM_BYTES>>>(
                fRp, fXmp, fX, nullptr, fXp, fXm, fB0, gammas + i, 0);
        k_gemm<512, 1024, 2><<<dim3(BB / 128, 8), 256, SMEM_BYTES>>>(
            fEp, fXp, nullptr, nullptr, fXsp, nullptr, nullptr, etas + i, (i == TT) ? 1 : 0);
        k_gemm<1024, 512, 3><<<dim3(BB / 128, 4), 256, SMEM_BYTES>>>(
            fDp, fXsp, fXm, nullptr, fXmp, fX, nullptr, nullptr, 0);
    }
    k_final<<<2 * BB * KD / 256, 256>>>(out);
    k_scalars<<<1, 32>>>(out);
}

// round 9
// speedup vs baseline: 1.3749x; 1.3749x over previous
#include <cuda_runtime.h>
#include <cstdint>
#include <math.h>

#define BB 8192
#define KD 256     // complex dim K
#define MD 1024    // sparse dim M
#define TT 10

#define LDA 36               // padded smem row stride (floats)
#define TSZ (128 * LDA)      // one tile (floats)
#define SMEM_FLOATS (4 * TSZ)          // A/X x 2 stages
#define SMEM_BYTES (SMEM_FLOATS * 4)   // 73728

// ---------------- scratch ----------------
__device__ float g_x[BB * 512];          // x    [b][2K]
__device__ float g_xmap[BB * 512];       // xmap [b][2K]
__device__ float g_b0[BB * 512];         // b0   [b][2K]
__device__ float g_xsp[(size_t)BB * MD]; // xsp  [b][M]
__device__ float g_R[512 * 512];
__device__ float g_WXr[512 * 256];
__device__ float g_E[MD * 512];
__device__ float g_D[512 * MD];
__device__ float g_acc[3];

// ---------------- asm helpers ----------------
__device__ __forceinline__ uint32_t smem_u32(const void* p) {
    uint32_t a;
    asm("{ .reg .u64 t; cvta.to.shared.u64 t, %1; cvt.u32.u64 %0, t; }" : "=r"(a) : "l"(p));
    return a;
}
__device__ __forceinline__ void cp16(uint32_t dst, const void* src) {
    asm volatile("cp.async.cg.shared.global [%0], [%1], 16;" :: "r"(dst), "l"(src));
}
__device__ __forceinline__ void cp_commit() {
    asm volatile("cp.async.commit_group;" ::: "memory");
}
template <int N>
__device__ __forceinline__ void cp_wait() {
    asm volatile("cp.async.wait_group %0;" :: "n"(N) : "memory");
}
__device__ __forceinline__ void mma8(float* c, uint32_t a0, uint32_t a1, uint32_t a2, uint32_t a3,
                                     uint32_t b0, uint32_t b1) {
    asm volatile(
        "mma.sync.aligned.m16n8k8.row.col.f32.tf32.tf32.f32 "
        "{%0,%1,%2,%3}, {%4,%5,%6,%7}, {%8,%9}, {%0,%1,%2,%3};"
        : "+f"(c[0]), "+f"(c[1]), "+f"(c[2]), "+f"(c[3])
        : "r"(a0), "r"(a1), "r"(a2), "r"(a3), "r"(b0), "r"(b1));
}
// hi = round-to-nearest tf32 of v; lo = (v - hi) passed as RAW fp32 bits.
// tf32 MMA reads only the tf32 bit-subset of the register, so lo is
// effectively truncated toward zero: adds ~2^-21 relative error (negligible).
__device__ __forceinline__ void split1(float v, uint32_t& h, uint32_t& l) {
    uint32_t hb;
    asm("cvt.rna.tf32.f32 %0, %1;" : "=r"(hb) : "f"(v));
    h = hb;
    l = __float_as_uint(v - __uint_as_float(hb));
}

// ---------------- tensor-core GEMM: D[m][b] = A[m][:] . X[b][:] ----------------
// EPI: 0 = plain store, 1 = x-update, 2 = shrink(+L1,+count), 3 = xmap(+huber)
template <int KIN, int MOUT, int EPI>
__global__ void __launch_bounds__(256, 2) k_gemm(
    const float* __restrict__ A, const float* __restrict__ Xm, float* __restrict__ OUT,
    const float* __restrict__ aux1, const float* __restrict__ aux2,
    const float* __restrict__ scal, int last)
{
    extern __shared__ float sm[];
    float* As = sm;             // [2][128][LDA]
    float* Xs = sm + 2 * TSZ;   // [2][128][LDA]

    const int tid = threadIdx.x;
    const int wid = tid >> 5, lane = tid & 31;
    const int g = lane >> 2, tg = lane & 3;
    const int b0 = blockIdx.x * 128;
    const int m0 = blockIdx.y * 128;
    const int m_off = (wid & 1) * 64;
    const int n_off = (wid >> 1) * 32;

    constexpr int NS = KIN / 32;

    const int crow = tid >> 3, ccg = (tid & 7) * 4;   // copy indexing

    // issue stage st -> buf st&1
    auto issue = [&](int st) {
        const int kk = st * 32;
        float* Ao = As + (st & 1) * TSZ;
        float* Xo = Xs + (st & 1) * TSZ;
#pragma unroll
        for (int r = 0; r < 4; r++) {
            int rr = crow + 32 * r;
            cp16(smem_u32(Ao + rr * LDA + ccg), A + (size_t)(m0 + rr) * KIN + kk + ccg);
            cp16(smem_u32(Xo + rr * LDA + ccg), Xm + (size_t)(b0 + rr) * KIN + kk + ccg);
        }
        cp_commit();
    };

    float c[4][4][4];
#pragma unroll
    for (int i = 0; i < 4; i++)
#pragma unroll
        for (int j = 0; j < 4; j++)
#pragma unroll
            for (int q = 0; q < 4; q++) c[i][j][q] = 0.f;

    issue(0);
    issue(1);

    for (int kt = 0; kt < NS; kt++) {
        cp_wait<1>();
        __syncthreads();

        const int buf = kt & 1;
        const float* Ab = As + buf * TSZ;
        const float* Xb = Xs + buf * TSZ;
#pragma unroll
        for (int ks = 0; ks < 4; ks++) {
            const float* ap = Ab + (m_off + g) * LDA + ks * 8 + tg;
            const float* xp = Xb + (n_off + g) * LDA + ks * 8 + tg;
            uint32_t ah[4][4], al[4][4], xh[4][2], xl[4][2];
#pragma unroll
            for (int mf = 0; mf < 4; mf++) {
                split1(ap[mf * 16 * LDA],               ah[mf][0], al[mf][0]);
                split1(ap[mf * 16 * LDA + 8 * LDA],     ah[mf][1], al[mf][1]);
                split1(ap[mf * 16 * LDA + 4],           ah[mf][2], al[mf][2]);
                split1(ap[mf * 16 * LDA + 8 * LDA + 4], ah[mf][3], al[mf][3]);
            }
#pragma unroll
            for (int nf = 0; nf < 4; nf++) {
                split1(xp[nf * 8 * LDA],     xh[nf][0], xl[nf][0]);
                split1(xp[nf * 8 * LDA + 4], xh[nf][1], xl[nf][1]);
            }
#pragma unroll
            for (int mf = 0; mf < 4; mf++)
#pragma unroll
                for (int nf = 0; nf < 4; nf++) {
                    mma8(c[mf][nf], ah[mf][0], ah[mf][1], ah[mf][2], ah[mf][3], xh[nf][0], xh[nf][1]);
                    mma8(c[mf][nf], ah[mf][0], ah[mf][1], ah[mf][2], ah[mf][3], xl[nf][0], xl[nf][1]);
                    mma8(c[mf][nf], al[mf][0], al[mf][1], al[mf][2], al[mf][3], xh[nf][0], xh[nf][1]);
                }
        }
        __syncthreads();
        if (kt + 2 < NS) issue(kt + 2);
        else cp_commit();           // keep group count aligned for cp_wait<1>
    }

    // ---------------- epilogue ----------------
    float s_a = 0.f, s_b = 0.f;
    float gam = 0.f, eta = 0.f;
    if (EPI == 1) gam = scal[0];
    if (EPI == 2) eta = scal[0];
#pragma unroll
    for (int mf = 0; mf < 4; mf++)
#pragma unroll
        for (int nf = 0; nf < 4; nf++) {
#pragma unroll
            for (int q = 0; q < 4; q++) {
                int m = m0 + m_off + mf * 16 + g + (q >= 2 ? 8 : 0);
                int b = b0 + n_off + nf * 8 + tg * 2 + (q & 1);
                size_t o = (size_t)b * MOUT + m;
                float d = c[mf][nf][q];
                if (EPI == 0) {
                    OUT[o] = d;
                } else if (EPI == 1) {
                    OUT[o] = aux1[o] - gam * (d - aux2[o]);
                } else if (EPI == 2) {
                    float ad = fabsf(d) - eta;
                    float v = (ad > 0.f) ? copysignf(ad, d) : 0.f;
                    OUT[o] = v;
                    s_a += fabsf(v);
                    if (last) s_b += (fabsf(v) > 1e-3f) ? 1.f : 0.f;
                } else {
                    float xo = aux1[o];
                    float dd = xo - d; float ad = fabsf(dd);
                    s_a += (ad < 1.f) ? 0.5f * dd * dd : ad - 0.5f;
                    OUT[o] = d;
                }
            }
        }
    if (EPI == 2 || EPI == 3) {
#pragma unroll
        for (int off = 16; off > 0; off >>= 1) {
            s_a += __shfl_down_sync(0xffffffffu, s_a, off);
            if (EPI == 2) s_b += __shfl_down_sync(0xffffffffu, s_b, off);
        }
        if (lane == 0) {
            atomicAdd(&g_acc[EPI == 2 ? 0 : 1], s_a);
            if (EPI == 2 && last) atomicAdd(&g_acc[2], s_b);
        }
    }
}

// ---------------- prep kernels ----------------
__global__ void k_zero() { if (threadIdx.x < 3) g_acc[threadIdx.x] = 0.f; }

// R = real form of P = WX(2,256,128) @ W(2,128,256)
__global__ void k_prep_R(const float* __restrict__ W, const float* __restrict__ WX) {
    int j = blockIdx.x * 16 + threadIdx.x;   // 0..255
    int i = blockIdx.y * 16 + threadIdx.y;   // 0..255
    float pre = 0.f, pim = 0.f;
#pragma unroll 4
    for (int n = 0; n < 128; n++) {
        float ar = WX[i * 128 + n], ai = WX[32768 + i * 128 + n];
        float br = W[n * 256 + j],  bi = W[32768 + n * 256 + j];
        pre += ar * br - ai * bi;
        pim += ar * bi + ai * br;
    }
    g_R[i * 512 + j] = pre;
    g_R[i * 512 + j + 256] = -pim;
    g_R[(i + 256) * 512 + j] = pim;
    g_R[(i + 256) * 512 + j + 256] = pre;
}

__global__ void k_prep_WXr(const float* __restrict__ WX) {
    int idx = blockIdx.x * 256 + threadIdx.x;          // 512*256
    int np = idx & 255, j = idx >> 8;
    int jj = j & 255, jr = j >> 8;
    int nn = np & 127, nc = np >> 7;
    float re = WX[jj * 128 + nn], im = WX[32768 + jj * 128 + nn];
    float v;
    if (jr == 0) v = (nc == 0) ? re : -im;
    else         v = (nc == 0) ? im :  re;
    g_WXr[idx] = v;
}

__global__ void k_prep_E(const float* __restrict__ E0) {
    int idx = blockIdx.x * 256 + threadIdx.x;          // 1024*512
    int k = idx & 511, mrow = idx >> 9;
    g_E[idx] = (k < 256) ? E0[mrow * 256 + k] : -E0[262144 + mrow * 256 + (k - 256)];
}

__global__ void k_prep_D(const float* __restrict__ E0) {
    int idx = blockIdx.x * 256 + threadIdx.x;          // 512*1024
    int mrow = idx & 1023, j = idx >> 10;
    g_D[idx] = (j < 256) ? E0[mrow * 256 + j] : -E0[262144 + mrow * 256 + (j - 256)];
}

__global__ void k_x1(const float* __restrict__ gammas) {
    int idx = blockIdx.x * 256 + threadIdx.x;          // 8192*512
    g_x[idx] = gammas[1] * g_b0[idx];
}

__global__ void k_final(float* __restrict__ out) {
    int idx = blockIdx.x * 256 + threadIdx.x;          // 2*8192*256
    int k = idx & 255, b = (idx >> 8) & 8191, cch = idx >> 21;
    out[idx] = g_xmap[(size_t)b * 512 + cch * 256 + k];
}

__global__ void k_scalars(float* __restrict__ out) {
    if (threadIdx.x == 0 && blockIdx.x == 0) {
        size_t base = 2ull * BB * KD;
        out[base + 0] = g_acc[0] / (float)BB;
        out[base + 1] = g_acc[1] / ((float)2 * KD * BB * TT);
        out[base + 2] = g_acc[2] / (float)BB;
    }
}

// ---------------- launch ----------------
extern "C" void kernel_launch(void* const* d_in, const int* in_sizes, int n_in,
                              void* d_out, int out_size) {
    const float* y      = (const float*)d_in[0];
    const float* W      = (const float*)d_in[1];
    const float* WX     = (const float*)d_in[2];
    const float* E0     = (const float*)d_in[3];
    const float* etas   = (const float*)d_in[4];
    const float* gammas = (const float*)d_in[5];
    float* out = (float*)d_out;

    void *pR, *pWXr, *pE, *pD, *pX, *pXmap, *pB0, *pXsp;
    cudaGetSymbolAddress(&pR, g_R);
    cudaGetSymbolAddress(&pWXr, g_WXr);
    cudaGetSymbolAddress(&pE, g_E);
    cudaGetSymbolAddress(&pD, g_D);
    cudaGetSymbolAddress(&pX, g_x);
    cudaGetSymbolAddress(&pXmap, g_xmap);
    cudaGetSymbolAddress(&pB0, g_b0);
    cudaGetSymbolAddress(&pXsp, g_xsp);
    const float *fR = (const float*)pR, *fWXr = (const float*)pWXr;
    const float *fE = (const float*)pE, *fD = (const float*)pD;
    float *fX = (float*)pX, *fXmap = (float*)pXmap, *fB0 = (float*)pB0, *fXsp = (float*)pXsp;

    cudaFuncSetAttribute(k_gemm<256, 512, 0>, cudaFuncAttributeMaxDynamicSharedMemorySize, SMEM_BYTES);
    cudaFuncSetAttribute(k_gemm<512, 512, 1>, cudaFuncAttributeMaxDynamicSharedMemorySize, SMEM_BYTES);
    cudaFuncSetAttribute(k_gemm<512, 1024, 2>, cudaFuncAttributeMaxDynamicSharedMemorySize, SMEM_BYTES);
    cudaFuncSetAttribute(k_gemm<1024, 512, 3>, cudaFuncAttributeMaxDynamicSharedMemorySize, SMEM_BYTES);

    k_zero<<<1, 32>>>();
    k_prep_R<<<dim3(16, 16), dim3(16, 16)>>>(W, WX);
    k_prep_WXr<<<512 * 256 / 256, 256>>>(WX);
    k_prep_E<<<1024 * 512 / 256, 256>>>(E0);
    k_prep_D<<<512 * 1024 / 256, 256>>>(E0);

    // b0 = WXr . y  -> g_b0 [b][512]   (y is [b][2N] = [b][256] row-major, matches X layout)
    k_gemm<256, 512, 0><<<dim3(BB / 128, 4), 256, SMEM_BYTES>>>(fWXr, y, fB0,
        nullptr, nullptr, nullptr, 0);
    k_x1<<<BB * 512 / 256, 256>>>(gammas);

    for (int i = 1; i <= TT; i++) {
        if (i > 1)
            k_gemm<512, 512, 1><<<dim3(BB / 128, 4), 256, SMEM_BYTES>>>(fR, fXmap, fX,
                fXmap, fB0, gammas + i, 0);
        k_gemm<512, 1024, 2><<<dim3(BB / 128, 8), 256, SMEM_BYTES>>>(fE, fX, fXsp,
            nullptr, nullptr, etas + i, (i == TT) ? 1 : 0);
        k_gemm<1024, 512, 3><<<dim3(BB / 128, 4), 256, SMEM_BYTES>>>(fD, fXsp, fXmap,
            fX, nullptr, nullptr, 0);
    }
    k_final<<<2 * BB * KD / 256, 256>>>(out);
    k_scalars<<<1, 32>>>(out);
}